// round 1
// baseline (speedup 1.0000x reference)
#include <cuda_runtime.h>

#define INV_CELL 20.0f

// Cubic B-spline basis + gradient for the 4 stencil offsets along one dim.
// f = fractional coordinate in [0,1). Offset m gives x = f + 1 - m, which
// deterministically falls in branch: m=0 -> [1,2), m=1 -> [0,1),
// m=2 -> [-1,0), m=3 -> [-2,-1). Polynomials copied verbatim from reference.
__device__ __forceinline__ void splines4(float f, float b[4], float db[4]) {
    const float h = INV_CELL;
    float x0 = f + 1.0f;   // c4: [1,2)
    b[0]  = ((-1.0f/6.0f * x0 + 1.0f) * x0 - 2.0f) * x0 + 4.0f/3.0f;
    db[0] = h * ((-0.5f * x0 + 2.0f) * x0 - 2.0f);
    float x1 = f;          // c3: [0,1)
    b[1]  = (0.5f * x1 - 1.0f) * x1 * x1 + 2.0f/3.0f;
    db[1] = h * (1.5f * x1 - 2.0f) * x1;
    float x2 = f - 1.0f;   // c2: [-1,0)
    b[2]  = (-0.5f * x2 - 1.0f) * x2 * x2 + 2.0f/3.0f;
    db[2] = h * (-1.5f * x2 - 2.0f) * x2;
    float x3 = f - 2.0f;   // c1: [-2,-1)
    b[3]  = ((1.0f/6.0f * x3 + 1.0f) * x3 + 2.0f) * x3 + 4.0f/3.0f;
    db[3] = h * ((0.5f * x3 + 2.0f) * x3 + 2.0f);
}

// 16 threads per point: thread sub = i*4 + j handles (i, j, k=0..3).
// Writes: 1 float4 of shapef + 3 float4 of grad, all coalesced STG.128.
__global__ void cubic_shape_kernel(const float* __restrict__ pos,
                                   float* __restrict__ out_sf,
                                   float* __restrict__ out_grad,
                                   int n_points) {
    int gid = blockIdx.x * blockDim.x + threadIdx.x;
    int n = gid >> 4;
    if (n >= n_points) return;
    int sub = gid & 15;
    int i = sub >> 2;
    int j = sub & 3;

    float px = __ldg(&pos[n * 3 + 0]);
    float py = __ldg(&pos[n * 3 + 1]);
    float pz = __ldg(&pos[n * 3 + 2]);

    float rx = px * INV_CELL, ry = py * INV_CELL, rz = pz * INV_CELL;
    float fx = rx - floorf(rx);
    float fy = ry - floorf(ry);
    float fz = rz - floorf(rz);

    float b0[4], db0[4], b1[4], db1[4], b2[4], db2[4];
    splines4(fx, b0, db0);
    splines4(fy, b1, db1);
    splines4(fz, b2, db2);

    float bi = b0[i],  dbi = db0[i];
    float bj = b1[j],  dbj = db1[j];
    float bij = bi * bj;

    // shapef: 4 consecutive stencil entries (i*16 + j*4 + k), k=0..3
    float4 sf;
    sf.x = bij * b2[0];
    sf.y = bij * b2[1];
    sf.z = bij * b2[2];
    sf.w = bij * b2[3];
    reinterpret_cast<float4*>(out_sf)[n * 16 + sub] = sf;

    // grad: 12 consecutive floats at ((n*64 + sub*4)*3), 48B per thread, 16B aligned
    float g[12];
    float dbi_bj = dbi * bj;
    float bi_dbj = bi * dbj;
#pragma unroll
    for (int k = 0; k < 4; k++) {
        float bk = b2[k];
        g[k * 3 + 0] = dbi_bj * bk;
        g[k * 3 + 1] = bi_dbj * bk;
        g[k * 3 + 2] = bij * db2[k];
    }
    float4* gdst = reinterpret_cast<float4*>(out_grad) + (size_t)(n * 16 + sub) * 3;
    gdst[0] = make_float4(g[0], g[1], g[2], g[3]);
    gdst[1] = make_float4(g[4], g[5], g[6], g[7]);
    gdst[2] = make_float4(g[8], g[9], g[10], g[11]);
}

extern "C" void kernel_launch(void* const* d_in, const int* in_sizes, int n_in,
                              void* d_out, int out_size) {
    const float* pos = (const float*)d_in[0];
    int n_points = in_sizes[0] / 3;

    float* out_sf = (float*)d_out;                       // [N, 64]
    float* out_grad = out_sf + (size_t)n_points * 64;    // [N, 64, 3]

    int total = n_points * 16;
    int block = 256;
    int grid = (total + block - 1) / block;
    cubic_shape_kernel<<<grid, block>>>(pos, out_sf, out_grad, n_points);
}

// round 2
// speedup vs baseline: 1.6119x; 1.6119x over previous
#include <cuda_runtime.h>

#define INV_CELL 20.0f
#define PTS 32           // points per block
#define NTHREADS 128
#define SF_STRIDE 17     // float4 per sf row  (16 + 1 pad -> kill bank conflicts)
#define GR_STRIDE 49     // float4 per grad row (48 + 1 pad)

// Cubic B-spline basis + gradient for the 4 stencil offsets along one dim.
// f = fractional coordinate in [0,1). Offset m gives x = f + 1 - m, which
// deterministically falls in branch: m=0 -> [1,2), m=1 -> [0,1),
// m=2 -> [-1,0), m=3 -> [-2,-1). Polynomials verbatim from reference.
__device__ __forceinline__ void splines4(float f, float b[4], float db[4]) {
    const float h = INV_CELL;
    float x0 = f + 1.0f;   // c4: [1,2)
    b[0]  = ((-1.0f/6.0f * x0 + 1.0f) * x0 - 2.0f) * x0 + 4.0f/3.0f;
    db[0] = h * ((-0.5f * x0 + 2.0f) * x0 - 2.0f);
    float x1 = f;          // c3: [0,1)
    b[1]  = (0.5f * x1 - 1.0f) * x1 * x1 + 2.0f/3.0f;
    db[1] = h * (1.5f * x1 - 2.0f) * x1;
    float x2 = f - 1.0f;   // c2: [-1,0)
    b[2]  = (-0.5f * x2 - 1.0f) * x2 * x2 + 2.0f/3.0f;
    db[2] = h * (-1.5f * x2 - 2.0f) * x2;
    float x3 = f - 2.0f;   // c1: [-2,-1)
    b[3]  = ((1.0f/6.0f * x3 + 1.0f) * x3 + 2.0f) * x3 + 4.0f/3.0f;
    db[3] = h * ((0.5f * x3 + 2.0f) * x3 + 2.0f);
}

__global__ void __launch_bounds__(NTHREADS)
cubic_shape_kernel(const float* __restrict__ pos,
                   float* __restrict__ out_sf,
                   float* __restrict__ out_grad,
                   int n_points) {
    __shared__ float4 sf_s[PTS * SF_STRIDE];   // 8704 B
    __shared__ float4 gr_s[PTS * GR_STRIDE];   // 25088 B

    int tid = threadIdx.x;
    int g = tid >> 2;        // local point 0..31
    int i = tid & 3;         // x-stencil index owned by this thread
    int n = blockIdx.x * PTS + g;

    // ---- compute phase: 4 threads per point, each handles one i ----
    if (n < n_points) {
        float px = __ldg(&pos[n * 3 + 0]);
        float py = __ldg(&pos[n * 3 + 1]);
        float pz = __ldg(&pos[n * 3 + 2]);

        float rx = px * INV_CELL, ry = py * INV_CELL, rz = pz * INV_CELL;
        float fx = rx - floorf(rx);
        float fy = ry - floorf(ry);
        float fz = rz - floorf(rz);

        float bx[4], dbx[4], by[4], dby[4], bz[4], dbz[4];
        splines4(fx, bx, dbx);
        splines4(fy, by, dby);
        splines4(fz, bz, dbz);

        // pick own i via SELs (no dynamic register indexing)
        float bi  = (i == 0) ? bx[0]  : (i == 1) ? bx[1]  : (i == 2) ? bx[2]  : bx[3];
        float dbi = (i == 0) ? dbx[0] : (i == 1) ? dbx[1] : (i == 2) ? dbx[2] : dbx[3];

#pragma unroll
        for (int j = 0; j < 4; j++) {
            float bj = by[j], dbj = dby[j];
            float bij    = bi * bj;
            float dbi_bj = dbi * bj;
            float bi_dbj = bi * dbj;

            // shapef: stencil entries (i,j,k=0..3) -> float4 index i*4+j within point
            sf_s[g * SF_STRIDE + i * 4 + j] =
                make_float4(bij * bz[0], bij * bz[1], bij * bz[2], bij * bz[3]);

            // grad: floats (k*3+c), k=0..3, c=0..2 -> 3 float4 at i*12 + j*3
            float gg[12];
#pragma unroll
            for (int k = 0; k < 4; k++) {
                gg[k * 3 + 0] = dbi_bj * bz[k];
                gg[k * 3 + 1] = bi_dbj * bz[k];
                gg[k * 3 + 2] = bij * dbz[k];
            }
            int base = g * GR_STRIDE + i * 12 + j * 3;
            gr_s[base + 0] = make_float4(gg[0], gg[1], gg[2],  gg[3]);
            gr_s[base + 1] = make_float4(gg[4], gg[5], gg[6],  gg[7]);
            gr_s[base + 2] = make_float4(gg[8], gg[9], gg[10], gg[11]);
        }
    }
    __syncthreads();

    // ---- copy-out phase: perfectly coalesced float4 stores ----
    // sf: PTS*16 = 512 float4 per block
    {
        int   blk_base = blockIdx.x * (PTS * 16);
        int   total    = n_points * 16;
        float4* dst    = reinterpret_cast<float4*>(out_sf);
#pragma unroll
        for (int p = 0; p < 4; p++) {
            int idx  = p * NTHREADS + tid;        // 0..511
            int gidx = blk_base + idx;
            if (gidx < total) {
                int pt = idx >> 4, q = idx & 15;
                dst[gidx] = sf_s[pt * SF_STRIDE + q];
            }
        }
    }
    // grad: PTS*48 = 1536 float4 per block
    {
        int   blk_base = blockIdx.x * (PTS * 48);
        int   total    = n_points * 48;
        float4* dst    = reinterpret_cast<float4*>(out_grad);
#pragma unroll
        for (int p = 0; p < 12; p++) {
            int idx  = p * NTHREADS + tid;        // 0..1535
            int gidx = blk_base + idx;
            if (gidx < total) {
                int pt = idx / 48;
                int q  = idx - pt * 48;
                dst[gidx] = gr_s[pt * GR_STRIDE + q];
            }
        }
    }
}

extern "C" void kernel_launch(void* const* d_in, const int* in_sizes, int n_in,
                              void* d_out, int out_size) {
    const float* pos = (const float*)d_in[0];
    int n_points = in_sizes[0] / 3;

    float* out_sf   = (float*)d_out;                      // [N, 64]
    float* out_grad = out_sf + (size_t)n_points * 64;     // [N, 64, 3]

    int grid = (n_points + PTS - 1) / PTS;
    cubic_shape_kernel<<<grid, NTHREADS>>>(pos, out_sf, out_grad, n_points);
}

// round 3
// speedup vs baseline: 2.0972x; 1.3011x over previous
#include <cuda_runtime.h>

#define INV_CELL 20.0f
#define PTS 32           // points per block
#define NTHREADS 128
#define GR_STRIDE 49     // float4 per grad row (48 + 1 pad -> kill bank conflicts)

// Cubic B-spline basis + gradient for the 4 stencil offsets along one dim.
// f = fractional coordinate in [0,1). Offset m gives x = f + 1 - m, which
// deterministically falls in branch: m=0 -> [1,2), m=1 -> [0,1),
// m=2 -> [-1,0), m=3 -> [-2,-1). Polynomials verbatim from reference.
__device__ __forceinline__ void splines4(float f, float b[4], float db[4]) {
    const float h = INV_CELL;
    float x0 = f + 1.0f;   // c4: [1,2)
    b[0]  = ((-1.0f/6.0f * x0 + 1.0f) * x0 - 2.0f) * x0 + 4.0f/3.0f;
    db[0] = h * ((-0.5f * x0 + 2.0f) * x0 - 2.0f);
    float x1 = f;          // c3: [0,1)
    b[1]  = (0.5f * x1 - 1.0f) * x1 * x1 + 2.0f/3.0f;
    db[1] = h * (1.5f * x1 - 2.0f) * x1;
    float x2 = f - 1.0f;   // c2: [-1,0)
    b[2]  = (-0.5f * x2 - 1.0f) * x2 * x2 + 2.0f/3.0f;
    db[2] = h * (-1.5f * x2 - 2.0f) * x2;
    float x3 = f - 2.0f;   // c1: [-2,-1)
    b[3]  = ((1.0f/6.0f * x3 + 1.0f) * x3 + 2.0f) * x3 + 4.0f/3.0f;
    db[3] = h * ((0.5f * x3 + 2.0f) * x3 + 2.0f);
}

__global__ void __launch_bounds__(NTHREADS)
cubic_shape_kernel(const float* __restrict__ pos,
                   float* __restrict__ out_sf,
                   float* __restrict__ out_grad,
                   int n_points) {
    __shared__ float4 gr_s[PTS * GR_STRIDE];   // 25088 B

    int tid = threadIdx.x;
    int g = tid >> 2;        // local point 0..31
    int i = tid & 3;         // stencil sub-index owned by this thread
    int n = blockIdx.x * PTS + g;

    if (n < n_points) {
        float px = __ldg(&pos[n * 3 + 0]);
        float py = __ldg(&pos[n * 3 + 1]);
        float pz = __ldg(&pos[n * 3 + 2]);

        float rx = px * INV_CELL, ry = py * INV_CELL, rz = pz * INV_CELL;
        float fx = rx - floorf(rx);
        float fy = ry - floorf(ry);
        float fz = rz - floorf(rz);

        float bx[4], dbx[4], by[4], dby[4], bz[4], dbz[4];
        splines4(fx, bx, dbx);
        splines4(fy, by, dby);
        splines4(fz, bz, dbz);

        // value at own index i via SELs (no dynamic register indexing)
        float byi = (i == 0) ? by[0]  : (i == 1) ? by[1]  : (i == 2) ? by[2]  : by[3];
        float bxi = (i == 0) ? bx[0]  : (i == 1) ? bx[1]  : (i == 2) ? bx[2]  : bx[3];
        float dbxi= (i == 0) ? dbx[0] : (i == 1) ? dbx[1] : (i == 2) ? dbx[2] : dbx[3];

        // ---- sf: direct stores. Thread owns float4 indices {4p + i}, p=0..3
        //      (x-index = p, y-index = i). Per-warp: 8 contiguous 64B runs. ----
        float4* sfp = reinterpret_cast<float4*>(out_sf) + (size_t)n * 16;
#pragma unroll
        for (int p = 0; p < 4; p++) {
            float bpi = bx[p] * byi;
            __stcs(&sfp[4 * p + i],
                   make_float4(bpi * bz[0], bpi * bz[1], bpi * bz[2], bpi * bz[3]));
        }

        // ---- grad: stage in smem (x-index = i owned by this thread) ----
#pragma unroll
        for (int j = 0; j < 4; j++) {
            float bj = by[j], dbj = dby[j];
            float bij    = bxi * bj;
            float dbi_bj = dbxi * bj;
            float bi_dbj = bxi * dbj;

            float gg[12];
#pragma unroll
            for (int k = 0; k < 4; k++) {
                gg[k * 3 + 0] = dbi_bj * bz[k];
                gg[k * 3 + 1] = bi_dbj * bz[k];
                gg[k * 3 + 2] = bij * dbz[k];
            }
            int base = g * GR_STRIDE + i * 12 + j * 3;
            gr_s[base + 0] = make_float4(gg[0], gg[1], gg[2],  gg[3]);
            gr_s[base + 1] = make_float4(gg[4], gg[5], gg[6],  gg[7]);
            gr_s[base + 2] = make_float4(gg[8], gg[9], gg[10], gg[11]);
        }
    }
    __syncthreads();

    // ---- grad copy-out: perfectly coalesced float4 streaming stores ----
    // PTS*48 = 1536 float4 per block; smem addr = idx + idx/48 (stride 49 = 48+1)
    {
        int   blk_base = blockIdx.x * (PTS * 48);
        int   total    = n_points * 48;
        float4* dst    = reinterpret_cast<float4*>(out_grad);
#pragma unroll
        for (int p = 0; p < 12; p++) {
            int idx  = p * NTHREADS + tid;        // 0..1535
            int gidx = blk_base + idx;
            if (gidx < total) {
                __stcs(&dst[gidx], gr_s[idx + idx / 48]);
            }
        }
    }
}

extern "C" void kernel_launch(void* const* d_in, const int* in_sizes, int n_in,
                              void* d_out, int out_size) {
    const float* pos = (const float*)d_in[0];
    int n_points = in_sizes[0] / 3;

    float* out_sf   = (float*)d_out;                      // [N, 64]
    float* out_grad = out_sf + (size_t)n_points * 64;     // [N, 64, 3]

    int grid = (n_points + PTS - 1) / PTS;
    cubic_shape_kernel<<<grid, NTHREADS>>>(pos, out_sf, out_grad, n_points);
}

// round 6
// speedup vs baseline: 2.1370x; 1.0190x over previous
#include <cuda_runtime.h>

#define INV_CELL 20.0f
#define PTS 16           // points per block
#define NTHREADS 128     // 8 threads per point
#define SF_STRIDE 17     // float4 per sf row  (16 + 1 pad)
#define GR_STRIDE 49     // float4 per grad row (48 + 1 pad)

// Cubic B-spline basis + gradient for a single stencil offset m (0..3).
// x = f + 1 - m deterministically falls in branch: m=0 -> [1,2), m=1 -> [0,1),
// m=2 -> [-1,0), m=3 -> [-2,-1). Coefficient sets selected branch-free; the
// FMA chains are identical in shape to the reference polynomials.
__device__ __forceinline__ void spline1(float f, int m, float& b, float& db) {
    float x  = f + (float)(1 - m);
    float a3 = (m == 0) ? -1.0f/6.0f : (m == 1) ? 0.5f : (m == 2) ? -0.5f : 1.0f/6.0f;
    float a2 = (m == 0 || m == 3) ? 1.0f : -1.0f;
    float a1 = (m == 0) ? -2.0f : (m == 3) ? 2.0f : 0.0f;
    float a0 = (m == 0 || m == 3) ? 4.0f/3.0f : 2.0f/3.0f;
    float d2 = (m == 0) ? -0.5f : (m == 1) ? 1.5f : (m == 2) ? -1.5f : 0.5f;
    float d1 = (m == 0 || m == 3) ? 2.0f : -2.0f;
    float d0 = (m == 0) ? -2.0f : (m == 3) ? 2.0f : 0.0f;
    b  = ((a3 * x + a2) * x + a1) * x + a0;
    db = INV_CELL * ((d2 * x + d1) * x + d0);
}

__global__ void __launch_bounds__(NTHREADS, 12)
cubic_shape_kernel(const float* __restrict__ pos,
                   float* __restrict__ out_sf,
                   float* __restrict__ out_grad,
                   int n_points) {
    __shared__ float4 sf_s[PTS * SF_STRIDE];   //  4352 B
    __shared__ float4 gr_s[PTS * GR_STRIDE];   // 12544 B

    int tid = threadIdx.x;
    int g   = tid >> 3;        // local point 0..15
    int s   = tid & 7;
    int i   = s >> 1;          // x-stencil index owned by this thread
    int jh  = s & 1;           // y half: j in {2jh, 2jh+1}
    int n   = blockIdx.x * PTS + g;

    if (n < n_points) {
        float px = __ldg(&pos[n * 3 + 0]);
        float py = __ldg(&pos[n * 3 + 1]);
        float pz = __ldg(&pos[n * 3 + 2]);

        float rx = px * INV_CELL, ry = py * INV_CELL, rz = pz * INV_CELL;
        float fx = rx - floorf(rx);
        float fy = ry - floorf(ry);
        float fz = rz - floorf(rz);

        // z: all 4 offsets (compile-time coefs, same codegen as before)
        float bz[4], dbz[4];
#pragma unroll
        for (int m = 0; m < 4; m++) spline1(fz, m, bz[m], dbz[m]);

        // x: only own index i; y: only own pair {2jh, 2jh+1}
        float bxi, dbxi;  spline1(fx, i, bxi, dbxi);
        float by0, dby0;  spline1(fy, 2 * jh,     by0, dby0);
        float by1, dby1;  spline1(fy, 2 * jh + 1, by1, dby1);

#pragma unroll
        for (int t = 0; t < 2; t++) {
            int   j   = 2 * jh + t;
            float bj  = t ? by1  : by0;
            float dbj = t ? dby1 : dby0;
            float bij    = bxi * bj;
            float dbi_bj = dbxi * bj;
            float bi_dbj = bxi * dbj;

            // sf: stencil entries (i, j, k=0..3)
            sf_s[g * SF_STRIDE + i * 4 + j] =
                make_float4(bij * bz[0], bij * bz[1], bij * bz[2], bij * bz[3]);

            // grad: 12 floats (k, c) -> 3 float4 at i*12 + j*3
            float gg[12];
#pragma unroll
            for (int k = 0; k < 4; k++) {
                gg[k * 3 + 0] = dbi_bj * bz[k];
                gg[k * 3 + 1] = bi_dbj * bz[k];
                gg[k * 3 + 2] = bij * dbz[k];
            }
            int base = g * GR_STRIDE + i * 12 + j * 3;
            gr_s[base + 0] = make_float4(gg[0], gg[1], gg[2],  gg[3]);
            gr_s[base + 1] = make_float4(gg[4], gg[5], gg[6],  gg[7]);
            gr_s[base + 2] = make_float4(gg[8], gg[9], gg[10], gg[11]);
        }
    }
    __syncthreads();

    // ---- copy-out: perfectly coalesced float4 streaming stores ----
    // sf: PTS*16 = 256 float4 per block
    {
        int   blk_base = blockIdx.x * (PTS * 16);
        int   total    = n_points * 16;
        float4* dst    = reinterpret_cast<float4*>(out_sf);
#pragma unroll
        for (int p = 0; p < 2; p++) {
            int idx  = p * NTHREADS + tid;        // 0..255
            int gidx = blk_base + idx;
            if (gidx < total) {
                __stcs(&dst[gidx], sf_s[idx + (idx >> 4)]);   // stride 17 = 16+1
            }
        }
    }
    // grad: PTS*48 = 768 float4 per block
    {
        int   blk_base = blockIdx.x * (PTS * 48);
        int   total    = n_points * 48;
        float4* dst    = reinterpret_cast<float4*>(out_grad);
#pragma unroll
        for (int p = 0; p < 6; p++) {
            int idx  = p * NTHREADS + tid;        // 0..767
            int gidx = blk_base + idx;
            if (gidx < total) {
                __stcs(&dst[gidx], gr_s[idx + idx / 48]);     // stride 49 = 48+1
            }
        }
    }
}

extern "C" void kernel_launch(void* const* d_in, const int* in_sizes, int n_in,
                              void* d_out, int out_size) {
    const float* pos = (const float*)d_in[0];
    int n_points = in_sizes[0] / 3;

    float* out_sf   = (float*)d_out;                      // [N, 64]
    float* out_grad = out_sf + (size_t)n_points * 64;     // [N, 64, 3]

    int grid = (n_points + PTS - 1) / PTS;
    cubic_shape_kernel<<<grid, NTHREADS>>>(pos, out_sf, out_grad, n_points);
}